// round 15
// baseline (speedup 1.0000x reference)
#include <cuda_runtime.h>
#include <cuda_fp16.h>
#include <cstdint>

#define TT 128
#define FF 63
#define PP 64
#define NT 512

// fp16 weight image: [ks 0..11][s 0..7][j 0..7][lane 0..31] -> uint2
//   k: reg0 = ks*16 + 2c,+1 ; reg1 = +8  (c = lane&3)
//   col v = lane>>2; jl = s*16 + 4*(j&3) + (v>>1), type = (j>>2)*2 + (v&1)
__device__ uint2 g_WimgH[12 * 8 * 8 * 32];
__device__ float g_bias[512];

static __device__ __forceinline__ float th_(float x) {
    float r; asm("tanh.approx.f32 %0, %1;" : "=f"(r) : "f"(x)); return r;
}
static __device__ __forceinline__ float sg_(float x) { return fmaf(0.5f, th_(0.5f * x), 0.5f); }

// half-element offset of (row, k) inside one A fragment image (64 rows = 12288 halves)
static __device__ __forceinline__ int frag_off_h(int row, int k) {
    int mt = row >> 4, tr = row & 15, ks = k >> 4, kc = k & 15;
    int lane = ((tr & 7) << 2) | ((kc & 7) >> 1);
    int reg  = ((tr >> 3) & 1) | ((kc >> 3) << 1);
    return (((mt * 12 + ks) * 32 + lane) * 4 + reg) * 2 + (kc & 1);
}

static __device__ __forceinline__ void mma16(float* d, uint4 a, uint2 b) {
    asm volatile("mma.sync.aligned.m16n8k16.row.col.f32.f16.f16.f32 "
        "{%0,%1,%2,%3}, {%4,%5,%6,%7}, {%8,%9}, {%0,%1,%2,%3};"
        : "+f"(d[0]), "+f"(d[1]), "+f"(d[2]), "+f"(d[3])
        : "r"(a.x), "r"(a.y), "r"(a.z), "r"(a.w), "r"(b.x), "r"(b.y));
}

static __device__ __forceinline__ float wfold(const float* Wih, const float* Whh,
                                              const float* Wout, int g, int k) {
    return (k < 64) ? Wih[g * 64 + k]
                    : Whh[g * 128 + (k - 64)] + Wih[g * 64] * Wout[k - 64];
}

__global__ void setup_kernel(const float* __restrict__ Wih, const float* __restrict__ Whh,
                             const float* __restrict__ bih, const float* __restrict__ bhh,
                             const float* __restrict__ Wout, const float* __restrict__ bout) {
    int idx = blockIdx.x * blockDim.x + threadIdx.x;   // 0..24575
    if (idx < 24576) {
        int lane = idx & 31, j = (idx >> 5) & 7, s = (idx >> 8) & 7, ks = idx >> 11;
        int tpr = lane >> 2, c = lane & 3;
        int jl   = s * 16 + 4 * (j & 3) + (tpr >> 1);
        int type = (j >> 2) * 2 + (tpr & 1);
        int g = type * 128 + jl;
        int kb = ks * 16;
        __half2 lo = __floats2half2_rn(wfold(Wih, Whh, Wout, g, kb + 2 * c),
                                       wfold(Wih, Whh, Wout, g, kb + 2 * c + 1));
        __half2 hi = __floats2half2_rn(wfold(Wih, Whh, Wout, g, kb + 8 + 2 * c),
                                       wfold(Wih, Whh, Wout, g, kb + 8 + 2 * c + 1));
        uint2 o; o.x = *(uint32_t*)&lo; o.y = *(uint32_t*)&hi;
        g_WimgH[idx] = o;
        if (idx < 512)
            g_bias[idx] = bih[idx] + bhh[idx] + Wih[idx * 64] * bout[0];
    }
}

// Dynamic SMEM (floats):
//   [0, 6144)        A buffer 0 (fp16, 64 rows x 192 k = 24576 B)
//   [6144, 12288)    A buffer 1
//   [12288, 20736)   c-state f32, row*132 + jl
//   [20736, 21248)   bias[512]
//   [21248, 21376)   Wout[128]
//   [21376, 25600)   OACC: [half][parity][32*33]
#define SMF_TOTAL 25600

__global__ __launch_bounds__(NT, 1)
void lstm_mma(const float* __restrict__ x,  const float* __restrict__ z,
              const float* __restrict__ h0, const float* __restrict__ c0,
              const float* __restrict__ Wout, const float* __restrict__ bout,
              float* __restrict__ Y) {
    extern __shared__ float sm[];
    float*  CSTf  = sm + 12288;
    float*  BIASf = sm + 20736;
    float*  WOUTf = sm + 21248;
    float*  OACC4 = sm + 21376;

    const int tid = threadIdx.x;
    const int half = tid >> 8, t256 = tid & 255;
    const int s = t256 >> 5, lane = tid & 31;      // n-stripe 0..7
    const int tpr = lane >> 2, c = lane & 3;
    const int b0 = blockIdx.x * 64;
    const float bout0 = __ldg(bout);

    // ---- one-time init ----
    for (int e = tid; e < 512; e += NT) BIASf[e] = g_bias[e];
    for (int e = tid; e < 128; e += NT) WOUTf[e] = __ldg(&Wout[e]);
    __half* A0h = (__half*)sm;
    __half* A1h = (__half*)(sm + 6144);
    for (int e = tid; e < 8192; e += NT) {              // h0 -> A0 (k 64..191)
        int row = e >> 7, kk = e & 127;
        A0h[frag_off_h(row, 64 + kk)] = __float2half_rn(h0[(b0 + row) * 128 + kk]);
    }
    for (int e = tid; e < 64 * FF; e += NT) {           // z_0 -> A0 (k 1..63)
        int row = e / FF, f = e - row * FF;
        A0h[frag_off_h(row, 1 + f)] = __float2half_rn(z[((b0 + row) * TT + 64) * FF + f]);
    }
    if (tid < 64) {                                     // delta -> A0 col 0; A1 col 0 = 0
        int row = tid;
        float d = x[(b0 + row) * TT + (TT - 1)] - bout0;
        for (int jv = 0; jv < 128; ++jv)
            d -= h0[(b0 + row) * 128 + jv] * __ldg(&Wout[jv]);
        A0h[frag_off_h(row, 0)] = __float2half_rn(d);
        A1h[frag_off_h(row, 0)] = __float2half_rn(0.0f);
    }
    for (int e = tid; e < 8192; e += NT) {              // c0 -> c-state
        int row = e >> 7, jl = e & 127;
        CSTf[row * 132 + jl] = c0[(b0 + row) * 128 + jl];
    }
    __syncthreads();

    const uint2* wp = (const uint2*)g_WimgH;
    const int wbase = s * 256 + lane;
    const int mt0 = half * 2, mt1 = half * 2 + 1;

    uint2 bc[8], bn[8];
    #pragma unroll
    for (int j = 0; j < 8; ++j) bc[j] = __ldg(&wp[wbase + j * 32]);

    for (int t = 0; t < PP; ++t) {
        const uint4*  Acur = (const uint4*)(sm + (t & 1) * 6144);
        __half*       Anxt = (__half*)(sm + ((t + 1) & 1) * 6144);
        float*        OACC = OACC4 + half * 2112 + (t & 1) * 1056;

        // ---- prefetch z_{t+1} (regs, under the GEMM) ----
        float zreg[8];
        {
            int zrow = half * 32 + (t256 >> 3);
            #pragma unroll
            for (int i = 0; i < 8; ++i) {
                int f = (t256 & 7) * 8 + i;
                zreg[i] = (t < PP - 1 && f < FF)
                        ? z[((b0 + zrow) * TT + 64 + t + 1) * FF + f] : 0.0f;
            }
        }

        // ---- GEMM: D[32,512] per half, reads Acur ----
        float acc[2][8][4];
        #pragma unroll
        for (int m = 0; m < 2; ++m)
            #pragma unroll
            for (int j = 0; j < 8; ++j)
                #pragma unroll
                for (int k2 = 0; k2 < 4; ++k2) acc[m][j][k2] = 0.0f;

        #pragma unroll
        for (int ks = 0; ks < 12; ++ks) {
            int ksn = (ks == 11) ? 0 : ks + 1;     // rotate: tail loads next step's ks=0
            #pragma unroll
            for (int j = 0; j < 8; ++j)
                bn[j] = __ldg(&wp[ksn * 2048 + wbase + j * 32]);
            uint4 a0 = Acur[(mt0 * 12 + ks) * 32 + lane];
            uint4 a1 = Acur[(mt1 * 12 + ks) * 32 + lane];
            #pragma unroll
            for (int j = 0; j < 8; ++j) {
                mma16(acc[0][j], a0, bc[j]);
                mma16(acc[1][j], a1, bc[j]);
            }
            #pragma unroll
            for (int j = 0; j < 8; ++j) bc[j] = bn[j];
        }
        // NO barrier here: epilogue writes only Anxt / OACC(parity) / private CST

        // ---- epilogue: all 4 gates in-thread; h -> Anxt ----
        #pragma unroll
        for (int m = 0; m < 2; ++m) {
            #pragma unroll
            for (int j = 0; j < 4; ++j) {
                const int jl = s * 16 + 4 * j + c;
                const float bi = BIASf[jl],       bf = BIASf[128 + jl];
                const float bg = BIASf[256 + jl], bo = BIASf[384 + jl];
                const float wj = WOUTf[jl];
                float op0 = 0.0f, op1 = 0.0f;
                #pragma unroll
                for (int slot = 0; slot < 2; ++slot) {
                    float gi_ = acc[m][j][2 * slot];
                    float gf_ = acc[m][j][2 * slot + 1];
                    float gg_ = acc[m][j + 4][2 * slot];
                    float go_ = acc[m][j + 4][2 * slot + 1];
                    int row = half * 32 + m * 16 + tpr + slot * 8;
                    float i_ = sg_(gi_ + bi), f_ = sg_(gf_ + bf);
                    float g_ = th_(gg_ + bg), o_ = sg_(go_ + bo);
                    float cn = f_ * CSTf[row * 132 + jl] + i_ * g_;
                    CSTf[row * 132 + jl] = cn;
                    float hv = o_ * th_(cn);
                    Anxt[frag_off_h(row, 64 + jl)] = __float2half_rn(hv);
                    if (slot == 0) op0 = hv * wj; else op1 = hv * wj;
                }
                int rl0 = m * 16 + tpr, rl1 = rl0 + 8;
                if (j == 0) {
                    OACC[rl0 * 33 + s * 4 + c] = op0;
                    OACC[rl1 * 33 + s * 4 + c] = op1;
                } else {
                    OACC[rl0 * 33 + s * 4 + c] += op0;
                    OACC[rl1 * 33 + s * 4 + c] += op1;
                }
            }
        }

        // z_{t+1} scatter -> Anxt cols 1..63
        {
            int zrow = half * 32 + (t256 >> 3);
            #pragma unroll
            for (int i = 0; i < 8; ++i) {
                int f = (t256 & 7) * 8 + i;
                if (f < FF) Anxt[frag_off_h(zrow, 1 + f)] = __float2half_rn(zreg[i]);
            }
        }
        if (t == 1 && t256 < 32)   // kill stale delta in buffer 0 (it's Anxt during t=1)
            ((__half*)sm)[frag_off_h(half * 32 + t256, 0)] = __float2half_rn(0.0f);

        asm volatile("bar.sync %0, 256;" :: "r"(half + 1) : "memory");

        if (t256 < 32) {           // Y: sum 32 stripe partials (overlaps others' next MMA)
            const float* p = &OACC[t256 * 33];
            float ssum = 0.0f;
            #pragma unroll
            for (int u = 0; u < 32; ++u) ssum += p[u];
            Y[(b0 + half * 32 + t256) * PP + t] = ssum + bout0;
        }
    }
}

extern "C" void kernel_launch(void* const* d_in, const int* in_sizes, int n_in,
                              void* d_out, int out_size) {
    const float* x    = (const float*)d_in[0];
    const float* z    = (const float*)d_in[1];
    const float* h0   = (const float*)d_in[2];
    const float* c0   = (const float*)d_in[3];
    const float* Wih  = (const float*)d_in[4];
    const float* Whh  = (const float*)d_in[5];
    const float* bih  = (const float*)d_in[6];
    const float* bhh  = (const float*)d_in[7];
    const float* Wout = (const float*)d_in[8];
    const float* bout = (const float*)d_in[9];
    float* Y = (float*)d_out;

    setup_kernel<<<48, 512>>>(Wih, Whh, bih, bhh, Wout, bout);
    cudaFuncSetAttribute(lstm_mma, cudaFuncAttributeMaxDynamicSharedMemorySize,
                         SMF_TOTAL * 4);
    lstm_mma<<<128, NT, SMF_TOTAL * 4>>>(x, z, h0, c0, Wout, bout, Y);
}

// round 16
// speedup vs baseline: 1.1707x; 1.1707x over previous
#include <cuda_runtime.h>
#include <cuda_fp16.h>
#include <cstdint>

#define TT 128
#define FF 63
#define PP 64
#define NT 256          // threads per CTA
#define MR 32           // batch rows per CTA

// fp16 weight image: [ks 0..11][s 0..7][j 0..7][lane 0..31] -> uint2
//   k: reg0 = ks*16 + 2c,+1 ; reg1 = +8  (c = lane&3)
//   col v = lane>>2; jl = s*16 + 4*(j&3) + (v>>1), type = (j>>2)*2 + (v&1)
__device__ uint2 g_WimgH[12 * 8 * 8 * 32];
__device__ float g_bias[512];

static __device__ __forceinline__ float th_(float x) {
    float r; asm("tanh.approx.f32 %0, %1;" : "=f"(r) : "f"(x)); return r;
}
static __device__ __forceinline__ float sg_(float x) { return fmaf(0.5f, th_(0.5f * x), 0.5f); }

// half-element offset of (row, k) inside the A fragment image (32 rows)
static __device__ __forceinline__ int frag_off_h(int row, int k) {
    int mt = row >> 4, tr = row & 15, ks = k >> 4, kc = k & 15;
    int lane = ((tr & 7) << 2) | ((kc & 7) >> 1);
    int reg  = ((tr >> 3) & 1) | ((kc >> 3) << 1);
    return (((mt * 12 + ks) * 32 + lane) * 4 + reg) * 2 + (kc & 1);
}

static __device__ __forceinline__ void mma16(float* d, uint4 a, uint2 b) {
    asm volatile("mma.sync.aligned.m16n8k16.row.col.f32.f16.f16.f32 "
        "{%0,%1,%2,%3}, {%4,%5,%6,%7}, {%8,%9}, {%0,%1,%2,%3};"
        : "+f"(d[0]), "+f"(d[1]), "+f"(d[2]), "+f"(d[3])
        : "r"(a.x), "r"(a.y), "r"(a.z), "r"(a.w), "r"(b.x), "r"(b.y));
}

static __device__ __forceinline__ float wfold(const float* Wih, const float* Whh,
                                              const float* Wout, int g, int k) {
    return (k < 64) ? Wih[g * 64 + k]
                    : Whh[g * 128 + (k - 64)] + Wih[g * 64] * Wout[k - 64];
}

__global__ void setup_kernel(const float* __restrict__ Wih, const float* __restrict__ Whh,
                             const float* __restrict__ bih, const float* __restrict__ bhh,
                             const float* __restrict__ Wout, const float* __restrict__ bout) {
    int idx = blockIdx.x * blockDim.x + threadIdx.x;   // 0..24575
    if (idx < 24576) {
        int lane = idx & 31, j = (idx >> 5) & 7, s = (idx >> 8) & 7, ks = idx >> 11;
        int tpr = lane >> 2, c = lane & 3;
        int jl   = s * 16 + 4 * (j & 3) + (tpr >> 1);
        int type = (j >> 2) * 2 + (tpr & 1);
        int g = type * 128 + jl;
        int kb = ks * 16;
        __half2 lo = __floats2half2_rn(wfold(Wih, Whh, Wout, g, kb + 2 * c),
                                       wfold(Wih, Whh, Wout, g, kb + 2 * c + 1));
        __half2 hi = __floats2half2_rn(wfold(Wih, Whh, Wout, g, kb + 8 + 2 * c),
                                       wfold(Wih, Whh, Wout, g, kb + 8 + 2 * c + 1));
        uint2 o; o.x = *(uint32_t*)&lo; o.y = *(uint32_t*)&hi;
        g_WimgH[idx] = o;
        if (idx < 512)
            g_bias[idx] = bih[idx] + bhh[idx] + Wih[idx * 64] * bout[0];
    }
}

// Dynamic SMEM (floats), per CTA:
//   [0, 3072)      A fragments fp16 (32 rows x 192 k = 12288 B)
//   [3072, 7296)   c-state f32, row*132 + jl   (32 rows)
//   [7296, 7808)   bias[512]
//   [7808, 7936)   Wout[128]
//   [7936, 8992)   OACC 32x33 (padded)
#define SMF_TOTAL 8992

__global__ __launch_bounds__(NT, 2)
void lstm_mma(const float* __restrict__ x,  const float* __restrict__ z,
              const float* __restrict__ h0, const float* __restrict__ c0,
              const float* __restrict__ Wout, const float* __restrict__ bout,
              float* __restrict__ Y) {
    extern __shared__ float sm[];
    __half* A_H   = (__half*)sm;
    float*  CSTf  = sm + 3072;
    float*  BIASf = sm + 7296;
    float*  WOUTf = sm + 7808;
    float*  OACC  = sm + 7936;
    const uint4* Au = (const uint4*)sm;

    const int tid = threadIdx.x;
    const int s = tid >> 5, lane = tid & 31;       // n-stripe 0..7
    const int tpr = lane >> 2, c = lane & 3;
    const int b0 = blockIdx.x * MR;
    const float bout0 = __ldg(bout);

    // ---- one-time init ----
    for (int e = tid; e < 512; e += NT) BIASf[e] = g_bias[e];
    for (int e = tid; e < 128; e += NT) WOUTf[e] = __ldg(&Wout[e]);
    for (int e = tid; e < MR * 128; e += NT) {          // h0 -> A (k 64..191)
        int row = e >> 7, kk = e & 127;
        A_H[frag_off_h(row, 64 + kk)] = __float2half_rn(h0[(b0 + row) * 128 + kk]);
    }
    for (int e = tid; e < MR * FF; e += NT) {           // z_0 -> A (k 1..63)
        int row = e / FF, f = e - row * FF;
        A_H[frag_off_h(row, 1 + f)] = __float2half_rn(z[((b0 + row) * TT + 64) * FF + f]);
    }
    if (tid < MR) {                                     // delta -> A col 0
        int row = tid;
        float d = x[(b0 + row) * TT + (TT - 1)] - bout0;
        for (int jv = 0; jv < 128; ++jv)
            d -= h0[(b0 + row) * 128 + jv] * __ldg(&Wout[jv]);
        A_H[frag_off_h(row, 0)] = __float2half_rn(d);
    }
    for (int e = tid; e < MR * 128; e += NT) {          // c0 -> c-state
        int row = e >> 7, jl = e & 127;
        CSTf[row * 132 + jl] = c0[(b0 + row) * 128 + jl];
    }
    __syncthreads();

    const uint2* wp = (const uint2*)g_WimgH;
    const int wbase = s * 256 + lane;

    uint2 bc[8], bn[8];
    #pragma unroll
    for (int j = 0; j < 8; ++j) bc[j] = __ldg(&wp[wbase + j * 32]);

    for (int t = 0; t < PP; ++t) {
        // ---- prefetch z_{t+1} under the GEMM ----
        float zreg[8];
        {
            int zrow = tid >> 3;
            #pragma unroll
            for (int i = 0; i < 8; ++i) {
                int f = (tid & 7) * 8 + i;
                zreg[i] = (t < PP - 1 && f < FF)
                        ? z[((b0 + zrow) * TT + 64 + t + 1) * FF + f] : 0.0f;
            }
        }

        // ---- GEMM: D[32,512] ----
        float acc[2][8][4];
        #pragma unroll
        for (int m = 0; m < 2; ++m)
            #pragma unroll
            for (int j = 0; j < 8; ++j)
                #pragma unroll
                for (int k2 = 0; k2 < 4; ++k2) acc[m][j][k2] = 0.0f;

        #pragma unroll
        for (int ks = 0; ks < 12; ++ks) {
            int ksn = (ks == 11) ? 0 : ks + 1;     // rotate: tail loads next step's ks=0
            #pragma unroll
            for (int j = 0; j < 8; ++j)
                bn[j] = __ldg(&wp[ksn * 2048 + wbase + j * 32]);
            uint4 a0 = Au[(0 * 12 + ks) * 32 + lane];
            uint4 a1 = Au[(1 * 12 + ks) * 32 + lane];
            #pragma unroll
            for (int j = 0; j < 8; ++j) {
                mma16(acc[0][j], a0, bc[j]);
                mma16(acc[1][j], a1, bc[j]);
            }
            #pragma unroll
            for (int j = 0; j < 8; ++j) bc[j] = bn[j];
        }
        __syncthreads();   // A reads complete before epilogue overwrites A

        // ---- epilogue: all 4 gates in-thread; register output partials ----
        float opart[2][2] = {{0.0f, 0.0f}, {0.0f, 0.0f}};
        #pragma unroll
        for (int m = 0; m < 2; ++m) {
            #pragma unroll
            for (int j = 0; j < 4; ++j) {
                const int jl = s * 16 + 4 * j + c;
                const float bi = BIASf[jl],       bf = BIASf[128 + jl];
                const float bg = BIASf[256 + jl], bo = BIASf[384 + jl];
                const float wj = WOUTf[jl];
                #pragma unroll
                for (int slot = 0; slot < 2; ++slot) {
                    float gi_ = acc[m][j][2 * slot];
                    float gf_ = acc[m][j][2 * slot + 1];
                    float gg_ = acc[m][j + 4][2 * slot];
                    float go_ = acc[m][j + 4][2 * slot + 1];
                    int row = m * 16 + tpr + slot * 8;
                    float i_ = sg_(gi_ + bi), f_ = sg_(gf_ + bf);
                    float g_ = th_(gg_ + bg), o_ = sg_(go_ + bo);
                    float cn = f_ * CSTf[row * 132 + jl] + i_ * g_;
                    CSTf[row * 132 + jl] = cn;
                    float hv = o_ * th_(cn);
                    A_H[frag_off_h(row, 64 + jl)] = __float2half_rn(hv);
                    opart[m][slot] += hv * wj;
                }
            }
        }
        #pragma unroll
        for (int m = 0; m < 2; ++m)
            #pragma unroll
            for (int slot = 0; slot < 2; ++slot) {
                int rl = m * 16 + tpr + slot * 8;
                OACC[rl * 33 + s * 4 + c] = opart[m][slot];
            }

        // z_{t+1} scatter into A cols 1..63
        {
            int zrow = tid >> 3;
            #pragma unroll
            for (int i = 0; i < 8; ++i) {
                int f = (tid & 7) * 8 + i;
                if (f < FF) A_H[frag_off_h(zrow, 1 + f)] = __float2half_rn(zreg[i]);
            }
        }
        if (t == 0 && tid < MR)     // delta column dies after step 0
            A_H[frag_off_h(tid, 0)] = __float2half_rn(0.0f);
        __syncthreads();   // writes complete

        if (tid < MR) {    // Y: sum 32 stripe-partials
            const float* p = &OACC[tid * 33];
            float ssum = 0.0f;
            #pragma unroll
            for (int u = 0; u < 32; ++u) ssum += p[u];
            Y[(b0 + tid) * PP + t] = ssum + bout0;
        }
    }
}

extern "C" void kernel_launch(void* const* d_in, const int* in_sizes, int n_in,
                              void* d_out, int out_size) {
    const float* x    = (const float*)d_in[0];
    const float* z    = (const float*)d_in[1];
    const float* h0   = (const float*)d_in[2];
    const float* c0   = (const float*)d_in[3];
    const float* Wih  = (const float*)d_in[4];
    const float* Whh  = (const float*)d_in[5];
    const float* bih  = (const float*)d_in[6];
    const float* bhh  = (const float*)d_in[7];
    const float* Wout = (const float*)d_in[8];
    const float* bout = (const float*)d_in[9];
    float* Y = (float*)d_out;

    setup_kernel<<<48, 512>>>(Wih, Whh, bih, bhh, Wout, bout);
    cudaFuncSetAttribute(lstm_mma, cudaFuncAttributeMaxDynamicSharedMemorySize,
                         SMF_TOTAL * 4);
    lstm_mma<<<256, NT, SMF_TOTAL * 4>>>(x, z, h0, c0, Wout, bout, Y);
}